// round 1
// baseline (speedup 1.0000x reference)
#include <cuda_runtime.h>
#include <math.h>

#define B_  4
#define T_  4096
#define C_  1024
#define H_  64
#define SCALE 0.03125f   // C^-0.5 = 1/32 exactly

// ---------------- scratch (device globals: no allocation allowed) ----------
__device__ float g_q[B_ * T_ * H_];
__device__ float g_k[B_ * T_ * H_];
__device__ float g_v[B_ * T_ * H_];

// ---------------------------------------------------------------------------
// Kernel 1: fused QKV projection.
// Grid: (B*T)/64 = 256 CTAs. Each CTA: 64 rows x 192 cols (Q|K|V), K tiled by 64.
// 256 threads, thread micro-tile 4 rows x 12 cols (cols strided by 16).
// smem: xs[64][65] + ws[64][192]  = 65,792 B (dynamic).
// ---------------------------------------------------------------------------
#define QKV_SMEM ((64 * 65 + 64 * 192) * 4)

__global__ void __launch_bounds__(256, 2)
qkv_kernel(const float* __restrict__ x,
           const float* __restrict__ Wq,
           const float* __restrict__ Wk,
           const float* __restrict__ Wv)
{
    extern __shared__ float sm[];
    float (*xs)[65]  = (float (*)[65])sm;
    float (*ws)[192] = (float (*)[192])(sm + 64 * 65);

    const int tid = threadIdx.x;
    const int tx  = tid & 15;      // 0..15
    const int ty  = tid >> 4;      // 0..15
    const int row0 = blockIdx.x * 64;

    float acc[4][12];
#pragma unroll
    for (int r = 0; r < 4; r++)
#pragma unroll
        for (int c = 0; c < 12; c++) acc[r][c] = 0.f;

    for (int k0 = 0; k0 < C_; k0 += 64) {
        // load x tile 64x64 (float4, coalesced)
#pragma unroll
        for (int i = 0; i < 4; i++) {
            int idx = tid + i * 256;          // 0..1023 float4 slots
            int r = idx >> 4;
            int c = (idx & 15) << 2;
            float4 v = *(const float4*)(x + (size_t)(row0 + r) * C_ + k0 + c);
            xs[r][c + 0] = v.x; xs[r][c + 1] = v.y;
            xs[r][c + 2] = v.z; xs[r][c + 3] = v.w;
        }
        // load W tiles: Wq|Wk|Wv rows k0..k0+63, all 64 cols each
#pragma unroll
        for (int i = 0; i < 4; i++) {
            int idx = tid + i * 256;
            int r = idx >> 4;
            int c = (idx & 15) << 2;
            size_t off = (size_t)(k0 + r) * H_ + c;
            *(float4*)&ws[r][c]       = *(const float4*)(Wq + off);
            *(float4*)&ws[r][64 + c]  = *(const float4*)(Wk + off);
            *(float4*)&ws[r][128 + c] = *(const float4*)(Wv + off);
        }
        __syncthreads();

#pragma unroll
        for (int kk = 0; kk < 64; kk++) {
            float a[4], b[12];
#pragma unroll
            for (int r = 0; r < 4; r++) a[r] = xs[ty * 4 + r][kk];
#pragma unroll
            for (int c = 0; c < 12; c++) b[c] = ws[kk][tx + 16 * c];
#pragma unroll
            for (int r = 0; r < 4; r++)
#pragma unroll
                for (int c = 0; c < 12; c++)
                    acc[r][c] = fmaf(a[r], b[c], acc[r][c]);
        }
        __syncthreads();
    }

    // store to scratch
#pragma unroll
    for (int r = 0; r < 4; r++) {
        int grow = row0 + ty * 4 + r;
#pragma unroll
        for (int c = 0; c < 12; c++) {
            int col = tx + 16 * c;
            float* dst = (col < 64) ? g_q : (col < 128 ? g_k : g_v);
            dst[(size_t)grow * H_ + (col & 63)] = acc[r][c];
        }
    }
}

// ---------------------------------------------------------------------------
// Kernel 2: causal flash attention.
// Grid: (T/64, B) = (64, 4). Heavy tiles first via reversed blockIdx.x.
// 256 threads: thread grid 16x16; S micro-tile 4x4 (cols strided by 16),
// output micro-tile 4 rows x 4 of 64 head dims (strided by 16).
// smem: Qs,Ks,Vs,Ps each [64][65] = 66,560 B (dynamic).
// ---------------------------------------------------------------------------
#define ATTN_SMEM (4 * 64 * 65 * 4)

__global__ void __launch_bounds__(256, 2)
attn_kernel(float* __restrict__ out)
{
    extern __shared__ float sm[];
    float (*Qs)[65] = (float (*)[65])sm;
    float (*Ks)[65] = (float (*)[65])(sm + 64 * 65);
    float (*Vs)[65] = (float (*)[65])(sm + 2 * 64 * 65);
    float (*Ps)[65] = (float (*)[65])(sm + 3 * 64 * 65);

    const int tid = threadIdx.x;
    const int tx  = tid & 15;
    const int ty  = tid >> 4;
    const int qi  = (gridDim.x - 1) - blockIdx.x;  // heavy (large qi) first
    const int b   = blockIdx.y;
    const int qbase = qi * 64;
    const float* qp = g_q + (size_t)b * T_ * H_;
    const float* kp = g_k + (size_t)b * T_ * H_;
    const float* vp = g_v + (size_t)b * T_ * H_;

    // load Q tile
#pragma unroll
    for (int i = 0; i < 4; i++) {
        int idx = tid + i * 256;
        int r = idx >> 4;
        int c = (idx & 15) << 2;
        float4 v = *(const float4*)(qp + (size_t)(qbase + r) * H_ + c);
        Qs[r][c + 0] = v.x; Qs[r][c + 1] = v.y;
        Qs[r][c + 2] = v.z; Qs[r][c + 3] = v.w;
    }

    float m[4], l[4], acc[4][4];
#pragma unroll
    for (int r = 0; r < 4; r++) {
        m[r] = -INFINITY; l[r] = 0.f;
#pragma unroll
        for (int c = 0; c < 4; c++) acc[r][c] = 0.f;
    }

    const int ntiles = qi + 1;
    for (int j = 0; j < ntiles; j++) {
        // load K, V tiles
#pragma unroll
        for (int i = 0; i < 4; i++) {
            int idx = tid + i * 256;
            int r = idx >> 4;
            int c = (idx & 15) << 2;
            size_t off = (size_t)(j * 64 + r) * H_ + c;
            float4 kv = *(const float4*)(kp + off);
            Ks[r][c + 0] = kv.x; Ks[r][c + 1] = kv.y;
            Ks[r][c + 2] = kv.z; Ks[r][c + 3] = kv.w;
            float4 vv = *(const float4*)(vp + off);
            Vs[r][c + 0] = vv.x; Vs[r][c + 1] = vv.y;
            Vs[r][c + 2] = vv.z; Vs[r][c + 3] = vv.w;
        }
        __syncthreads();

        // S = Q K^T * scale   (s[r][c]: row = ty*4+r, key = tx+16*c)
        float s[4][4];
#pragma unroll
        for (int r = 0; r < 4; r++)
#pragma unroll
            for (int c = 0; c < 4; c++) s[r][c] = 0.f;
#pragma unroll
        for (int kk = 0; kk < 64; kk++) {
            float a[4], bb[4];
#pragma unroll
            for (int r = 0; r < 4; r++) a[r] = Qs[ty * 4 + r][kk];
#pragma unroll
            for (int c = 0; c < 4; c++) bb[c] = Ks[tx + 16 * c][kk];
#pragma unroll
            for (int r = 0; r < 4; r++)
#pragma unroll
                for (int c = 0; c < 4; c++)
                    s[r][c] = fmaf(a[r], bb[c], s[r][c]);
        }

        // scale + causal mask (only diagonal tile needs masking)
        if (j == qi) {
#pragma unroll
            for (int r = 0; r < 4; r++) {
                int qrow = qbase + ty * 4 + r;
#pragma unroll
                for (int c = 0; c < 4; c++) {
                    int key = j * 64 + tx + 16 * c;
                    s[r][c] = (key > qrow) ? -INFINITY : s[r][c] * SCALE;
                }
            }
        } else {
#pragma unroll
            for (int r = 0; r < 4; r++)
#pragma unroll
                for (int c = 0; c < 4; c++) s[r][c] *= SCALE;
        }

        // online softmax: row max/sum reduced across the 16 tx lanes
        float mnew[4], alpha[4], lt[4];
#pragma unroll
        for (int r = 0; r < 4; r++) {
            float mt = s[r][0];
#pragma unroll
            for (int c = 1; c < 4; c++) mt = fmaxf(mt, s[r][c]);
#pragma unroll
            for (int off = 8; off; off >>= 1)
                mt = fmaxf(mt, __shfl_xor_sync(0xffffffffu, mt, off));
            mnew[r] = fmaxf(m[r], mt);
            float ls = 0.f;
#pragma unroll
            for (int c = 0; c < 4; c++) {
                s[r][c] = __expf(s[r][c] - mnew[r]);   // exp(-inf)=0 for masked
                ls += s[r][c];
            }
#pragma unroll
            for (int off = 8; off; off >>= 1)
                ls += __shfl_xor_sync(0xffffffffu, ls, off);
            lt[r] = ls;
            alpha[r] = __expf(m[r] - mnew[r]);
            l[r] = l[r] * alpha[r] + lt[r];
            m[r] = mnew[r];
        }

        // stage P
#pragma unroll
        for (int r = 0; r < 4; r++)
#pragma unroll
            for (int c = 0; c < 4; c++)
                Ps[ty * 4 + r][tx + 16 * c] = s[r][c];
        __syncthreads();

        // O = O*alpha + P V   (out col = tx+16*c)
#pragma unroll
        for (int r = 0; r < 4; r++)
#pragma unroll
            for (int c = 0; c < 4; c++) acc[r][c] *= alpha[r];
#pragma unroll
        for (int kk = 0; kk < 64; kk++) {
            float a[4], bb[4];
#pragma unroll
            for (int r = 0; r < 4; r++) a[r] = Ps[ty * 4 + r][kk];
#pragma unroll
            for (int c = 0; c < 4; c++) bb[c] = Vs[kk][tx + 16 * c];
#pragma unroll
            for (int r = 0; r < 4; r++)
#pragma unroll
                for (int c = 0; c < 4; c++)
                    acc[r][c] = fmaf(a[r], bb[c], acc[r][c]);
        }
        __syncthreads();   // before next tile overwrites Ks/Vs/Ps
    }

    // normalize + write
#pragma unroll
    for (int r = 0; r < 4; r++) {
        int qrow = qbase + ty * 4 + r;
        float inv = 1.f / l[r];
#pragma unroll
        for (int c = 0; c < 4; c++) {
            int h = tx + 16 * c;
            out[((size_t)b * T_ + qrow) * H_ + h] = acc[r][c] * inv;
        }
    }
}

// ---------------------------------------------------------------------------
extern "C" void kernel_launch(void* const* d_in, const int* in_sizes, int n_in,
                              void* d_out, int out_size)
{
    const float* x  = (const float*)d_in[0];
    const float* Wq = (const float*)d_in[1];
    const float* Wk = (const float*)d_in[2];
    const float* Wv = (const float*)d_in[3];
    float* out = (float*)d_out;

    cudaFuncSetAttribute(qkv_kernel,  cudaFuncAttributeMaxDynamicSharedMemorySize, QKV_SMEM);
    cudaFuncSetAttribute(attn_kernel, cudaFuncAttributeMaxDynamicSharedMemorySize, ATTN_SMEM);

    qkv_kernel<<<(B_ * T_) / 64, 256, QKV_SMEM>>>(x, Wq, Wk, Wv);
    attn_kernel<<<dim3(T_ / 64, B_), 256, ATTN_SMEM>>>(out);
}